// round 2
// baseline (speedup 1.0000x reference)
#include <cuda_runtime.h>
#include <cstdint>

// ---------------------------------------------------------------------------
// Problem constants
// ---------------------------------------------------------------------------
#define T_STEPS 100
#define B_SZ    32
#define NIN     512
#define N_NEU   2048
#define A_AR    2
#define NC      4096                    // A*N output columns, c = a*2048+n
#define KROWS   4608                    // NIN + NC input rows
#define KCHUNK  144                     // 4608 / 32 k-chunks
#define NBY     8                       // k-splits across blocks
#define XIS_SZ  (T_STEPS * B_SZ * NIN)  // 1,638,400
#define SS_SZ   (T_STEPS * B_SZ * N_NEU)// 6,553,600 per area
// alpha = float32(exp(-0.1))
#define ALPHA_F 0.9048374180359595731642491f

// ---------------------------------------------------------------------------
// Device-global scratch (static — no allocation anywhere)
// ---------------------------------------------------------------------------
__device__ float g_W[KROWS * NC];               // fused weights [k][c], 75.5 MB
__device__ float g_sfin[T_STEPS * NIN * B_SZ];  // input spike floats [t][i][b]
__device__ float g_sfall[KROWS * B_SZ];         // per-step spike floats [k][b]
__device__ float g_V[NC * B_SZ];                // membrane V [c][b]
__device__ float g_P[NC * B_SZ * NBY];          // partials [c][b][by]

// ---------------------------------------------------------------------------
// Packed f32x2 helpers (sm_103a) — immune to fast-math contraction
// ---------------------------------------------------------------------------
__device__ __forceinline__ unsigned long long pack2(unsigned lo, unsigned hi) {
    unsigned long long d;
    asm("mov.b64 %0, {%1, %2};" : "=l"(d) : "r"(lo), "r"(hi));
    return d;
}
__device__ __forceinline__ unsigned long long ffma2(unsigned long long a,
                                                    unsigned long long b,
                                                    unsigned long long c) {
    unsigned long long d;
    asm("fma.rn.f32x2 %0, %1, %2, %3;" : "=l"(d) : "l"(a), "l"(b), "l"(c));
    return d;
}
__device__ __forceinline__ unsigned long long fadd2(unsigned long long a,
                                                    unsigned long long b) {
    unsigned long long d;
    asm("add.rn.f32x2 %0, %1, %2;" : "=l"(d) : "l"(a), "l"(b));
    return d;
}

// ---------------------------------------------------------------------------
// Kernel 1: Poisson input spikes for all T. Writes the Xis output region
// (exact match with reference: noise < rate*1e-3, all single f32 ops) and a
// transposed spike-float table g_sfin[t][i][b].
// ---------------------------------------------------------------------------
__global__ void __launch_bounds__(256) prep_spikes(const float* __restrict__ rates,
                                                   const float* __restrict__ noise,
                                                   float* __restrict__ out) {
    int idx = blockIdx.x * blockDim.x + threadIdx.x;
    if (idx >= XIS_SZ) return;
    int t = idx / (B_SZ * NIN);
    int r = idx - t * (B_SZ * NIN);
    int b = r / NIN;
    int i = r - b * NIN;
    float rt = rates[idx];
    float nz = noise[idx];
    float s = (nz < __fmul_rn(rt, 1e-3f)) ? 1.0f : 0.0f;
    out[idx] = s;
    g_sfin[(t * NIN + i) * B_SZ + b] = s;
}

// ---------------------------------------------------------------------------
// Kernel 2: fuse Win [A,NIN,N] and Wrec [S,A,N,N] into g_W[k][c].
//   k <  512 : g_W[k][a*2048+n] = Win[a][k][n]
//   k >= 512 : kr=k-512, s=kr>>11, m=kr&2047: g_W[k][a*2048+n] = Wrec[s][a][m][n]
// ---------------------------------------------------------------------------
__global__ void pack_w(const float* __restrict__ Win,
                       const float* __restrict__ Wrec) {
    const int total4 = KROWS * NC / 4;
    for (int idx = blockIdx.x * blockDim.x + threadIdx.x; idx < total4;
         idx += gridDim.x * blockDim.x) {
        int e = idx << 2;
        int k = e >> 12;              // / 4096
        int c = e & (NC - 1);
        int a = c >> 11;
        int n = c & (N_NEU - 1);
        float4 v;
        if (k < NIN) {
            v = *(const float4*)&Win[(a * NIN + k) * N_NEU + n];
        } else {
            int kr = k - NIN;
            int s  = kr >> 11;
            int m  = kr & (N_NEU - 1);
            v = *(const float4*)&Wrec[(((s * A_AR + a) * N_NEU) + m) * (size_t)N_NEU + n];
        }
        *(float4*)&g_W[e] = v;
    }
}

// ---------------------------------------------------------------------------
// Kernel 3: init state: V=0; spike table = [Xi(t=0) | zeros for rec rows]
// ---------------------------------------------------------------------------
__global__ void __launch_bounds__(256) init_state() {
    int idx = blockIdx.x * blockDim.x + threadIdx.x;
    if (idx < KROWS * B_SZ) {
        int k = idx >> 5;
        g_sfall[idx] = (k < NIN) ? g_sfin[idx] : 0.0f;  // g_sfin[(0*512+k)*32+b]
    }
    if (idx < NC * B_SZ) g_V[idx] = 0.0f;
}

// ---------------------------------------------------------------------------
// Kernel B (per step): binary-spike GEMM partials.
// Grid: (64 col-tiles, 8 k-splits). Block: 256 thr = 8 warps = (4 ksub x 2 bh).
// Warp: 64 columns (lane*2), 16 batches (8 f32x2 accumulators per column),
// k-range of 144. In-block reduce over ksub -> one partial per (c,b) per by.
// ---------------------------------------------------------------------------
__global__ void __launch_bounds__(256, 2) step_gemm() {
    __shared__ unsigned long long sbuf[8][32][17];  // 16 u64 + pad

    const int w    = threadIdx.x >> 5;
    const int lane = threadIdx.x & 31;
    const int bh   = w & 1;          // batch half: 0 -> b 0..15, 1 -> b 16..31
    const int ksub = w >> 1;         // 0..3
    const int c0   = blockIdx.x * 64 + lane * 2;
    const int kc   = blockIdx.y * 4 + ksub;     // 0..31
    const int k0   = kc * KCHUNK;
    const int k1   = k0 + KCHUNK;

    unsigned long long acc[2][8];
#pragma unroll
    for (int cc = 0; cc < 2; cc++)
#pragma unroll
        for (int j = 0; j < 8; j++) acc[cc][j] = 0ull;

#pragma unroll 2
    for (int k = k0; k < k1; k++) {
        float2 wv = *(const float2*)&g_W[k * NC + c0];
        const ulonglong2* sp = (const ulonglong2*)&g_sfall[k * B_SZ + bh * 16];
        ulonglong2 sA = sp[0], sB = sp[1], sC = sp[2], sD = sp[3];
        unsigned long long s2[8] = {sA.x, sA.y, sB.x, sB.y, sC.x, sC.y, sD.x, sD.y};
        unsigned wx = __float_as_uint(wv.x);
        unsigned wy = __float_as_uint(wv.y);
        unsigned long long w2a = pack2(wx, wx);
        unsigned long long w2b = pack2(wy, wy);
#pragma unroll
        for (int j = 0; j < 8; j++) {
            acc[0][j] = ffma2(w2a, s2[j], acc[0][j]);
            acc[1][j] = ffma2(w2b, s2[j], acc[1][j]);
        }
    }

    // stash to shared: 16 u64 per thread
#pragma unroll
    for (int cc = 0; cc < 2; cc++)
#pragma unroll
        for (int j = 0; j < 8; j++) sbuf[w][lane][cc * 8 + j] = acc[cc][j];
    __syncthreads();

    // warps with ksub==0 reduce the other three ksub partials (ascending order)
    if (ksub == 0) {
#pragma unroll
        for (int ks = 1; ks < 4; ks++) {
#pragma unroll
            for (int cc = 0; cc < 2; cc++)
#pragma unroll
                for (int j = 0; j < 8; j++)
                    acc[cc][j] = fadd2(acc[cc][j], sbuf[ks * 2 + bh][lane][cc * 8 + j]);
        }
        const int by = blockIdx.y;
#pragma unroll
        for (int cc = 0; cc < 2; cc++) {
            int c = c0 + cc;
#pragma unroll
            for (int j = 0; j < 8; j++) {
                unsigned long long v = acc[cc][j];
                float flo = __uint_as_float((unsigned)v);
                float fhi = __uint_as_float((unsigned)(v >> 32));
                int b = bh * 16 + 2 * j;
                g_P[(c * B_SZ + b) * NBY + by]     = flo;
                g_P[(c * B_SZ + b + 1) * NBY + by] = fhi;
            }
        }
    }
}

// ---------------------------------------------------------------------------
// Kernel C (per step): ordered reduce of 8 partials, LIF update, threshold,
// write spikes to output, refresh spike-float table for step t+1.
// ---------------------------------------------------------------------------
__global__ void __launch_bounds__(256) step_update(float* __restrict__ out, int t) {
    int idx = blockIdx.x * blockDim.x + threadIdx.x;   // 0 .. 131071
    if (idx >= NC * B_SZ) return;
    int c = idx >> 5;
    int b = idx & 31;

    const float4* p = (const float4*)&g_P[(size_t)idx * NBY];
    float4 u = p[0], v = p[1];
    float I = u.x;
    I = __fadd_rn(I, u.y);
    I = __fadd_rn(I, u.z);
    I = __fadd_rn(I, u.w);
    I = __fadd_rn(I, v.x);
    I = __fadd_rn(I, v.y);
    I = __fadd_rn(I, v.z);
    I = __fadd_rn(I, v.w);

    float xd   = g_sfall[(NIN + c) * B_SZ + b];   // previous spike of this neuron
    float Vold = g_V[idx];
    // V_new = ALPHA * V * (1 - Xd) + I, forced single-rounded f32 ops
    float Vnew = __fadd_rn(__fmul_rn(__fmul_rn(ALPHA_F, Vold), __fsub_rn(1.0f, xd)), I);
    float s = (Vnew >= 1.0f) ? 1.0f : 0.0f;

    g_V[idx] = Vnew;
    g_sfall[(NIN + c) * B_SZ + b] = s;            // recurrent rows for step t+1

    int a = c >> 11;
    int n = c & (N_NEU - 1);
    out[XIS_SZ + a * SS_SZ + t * (B_SZ * N_NEU) + b * N_NEU + n] = s;

    // feedforward rows for step t+1
    if (c < NIN && t + 1 < T_STEPS)
        g_sfall[c * B_SZ + b] = g_sfin[((t + 1) * NIN + c) * B_SZ + b];
}

// ---------------------------------------------------------------------------
// Launch: prep (3 kernels) + 100 x (gemm, update). All graph-capturable.
// ---------------------------------------------------------------------------
extern "C" void kernel_launch(void* const* d_in, const int* in_sizes, int n_in,
                              void* d_out, int out_size) {
    const float* rates = (const float*)d_in[0];
    const float* noise = (const float*)d_in[1];
    const float* Win   = (const float*)d_in[2];
    const float* Wrec  = (const float*)d_in[3];
    float* out = (float*)d_out;

    prep_spikes<<<(XIS_SZ + 255) / 256, 256>>>(rates, noise, out);
    pack_w<<<1024, 256>>>(Win, Wrec);
    init_state<<<(KROWS * B_SZ + 255) / 256, 256>>>();

    for (int t = 0; t < T_STEPS; t++) {
        step_gemm<<<dim3(NC / 64, NBY), 256>>>();
        step_update<<<(NC * B_SZ) / 256, 256>>>(out, t);
    }
}

// round 3
// speedup vs baseline: 1.9949x; 1.9949x over previous
#include <cuda_runtime.h>
#include <cstdint>

// ---------------------------------------------------------------------------
// Problem constants
// ---------------------------------------------------------------------------
#define T_STEPS 100
#define B_SZ    32
#define NIN     512
#define N_NEU   2048
#define A_AR    2
#define NC      4096                    // A*N output columns, c = a*2048+n
#define KROWS   4608                    // NIN + NC input rows
#define KCHUNK  144                     // 4608 / 32 k-chunks
#define NKC     32                      // number of k-chunks
#define NBY     8                       // k-splits across blocks (4 chunks each)
#define NBG     4                       // batch groups of 8
#define XIS_SZ  (T_STEPS * B_SZ * NIN)  // 1,638,400
#define SS_SZ   (T_STEPS * B_SZ * N_NEU)// 6,553,600 per area
// alpha = float32(exp(-0.1))
#define ALPHA_F 0.9048374180359595731642491f

// ---------------------------------------------------------------------------
// Device-global scratch (static — no allocation anywhere)
// ---------------------------------------------------------------------------
__device__ float    g_W[KROWS * NC];               // fused weights [k][c], 75.5 MB
__device__ float    g_sfin[T_STEPS * NIN * B_SZ];  // input spike floats [t][i][b]
__device__ float    g_sfall[KROWS * B_SZ];         // per-step spike floats [k][b]
__device__ float    g_V[NC * B_SZ];                // membrane V [c][b]
__device__ float    g_P[NC * B_SZ * NBY];          // partials [c][b][by]
// sparsity compaction: per (batch-group, k-chunk) ascending active-k lists
__device__ unsigned short g_list[NBG * NKC * KCHUNK];        // relative k (0..143)
__device__ float          g_spk[NBG * NKC * KCHUNK * 8];     // compacted spike floats
__device__ int            g_cnt[NBG * NKC];                  // active counts

// ---------------------------------------------------------------------------
// Packed f32x2 helpers (sm_103a) — immune to fast-math contraction
// ---------------------------------------------------------------------------
__device__ __forceinline__ unsigned long long pack2(unsigned lo, unsigned hi) {
    unsigned long long d;
    asm("mov.b64 %0, {%1, %2};" : "=l"(d) : "r"(lo), "r"(hi));
    return d;
}
__device__ __forceinline__ unsigned long long ffma2(unsigned long long a,
                                                    unsigned long long b,
                                                    unsigned long long c) {
    unsigned long long d;
    asm("fma.rn.f32x2 %0, %1, %2, %3;" : "=l"(d) : "l"(a), "l"(b), "l"(c));
    return d;
}
__device__ __forceinline__ unsigned long long fadd2(unsigned long long a,
                                                    unsigned long long b) {
    unsigned long long d;
    asm("add.rn.f32x2 %0, %1, %2;" : "=l"(d) : "l"(a), "l"(b));
    return d;
}

// ---------------------------------------------------------------------------
// Kernel 1: Poisson input spikes for all T. Writes the Xis output region and a
// transposed spike-float table g_sfin[t][i][b].
// ---------------------------------------------------------------------------
__global__ void __launch_bounds__(256) prep_spikes(const float* __restrict__ rates,
                                                   const float* __restrict__ noise,
                                                   float* __restrict__ out) {
    int idx = blockIdx.x * blockDim.x + threadIdx.x;
    if (idx >= XIS_SZ) return;
    int t = idx / (B_SZ * NIN);
    int r = idx - t * (B_SZ * NIN);
    int b = r / NIN;
    int i = r - b * NIN;
    float rt = rates[idx];
    float nz = noise[idx];
    float s = (nz < __fmul_rn(rt, 1e-3f)) ? 1.0f : 0.0f;
    out[idx] = s;
    g_sfin[(t * NIN + i) * B_SZ + b] = s;
}

// ---------------------------------------------------------------------------
// Kernel 2: fuse Win [A,NIN,N] and Wrec [S,A,N,N] into g_W[k][c].
// ---------------------------------------------------------------------------
__global__ void pack_w(const float* __restrict__ Win,
                       const float* __restrict__ Wrec) {
    const int total4 = KROWS * NC / 4;
    for (int idx = blockIdx.x * blockDim.x + threadIdx.x; idx < total4;
         idx += gridDim.x * blockDim.x) {
        int e = idx << 2;
        int k = e >> 12;              // / 4096
        int c = e & (NC - 1);
        int a = c >> 11;
        int n = c & (N_NEU - 1);
        float4 v;
        if (k < NIN) {
            v = *(const float4*)&Win[(a * NIN + k) * N_NEU + n];
        } else {
            int kr = k - NIN;
            int s  = kr >> 11;
            int m  = kr & (N_NEU - 1);
            v = *(const float4*)&Wrec[(((s * A_AR + a) * N_NEU) + m) * (size_t)N_NEU + n];
        }
        *(float4*)&g_W[e] = v;
    }
}

// ---------------------------------------------------------------------------
// Kernel 3: init state: V=0; spike table = [Xi(t=0) | zeros for rec rows]
// ---------------------------------------------------------------------------
__global__ void __launch_bounds__(256) init_state() {
    int idx = blockIdx.x * blockDim.x + threadIdx.x;
    if (idx < KROWS * B_SZ) {
        int k = idx >> 5;
        g_sfall[idx] = (k < NIN) ? g_sfin[idx] : 0.0f;
    }
    if (idx < NC * B_SZ) g_V[idx] = 0.0f;
}

// ---------------------------------------------------------------------------
// Kernel A (per step): compact active k per (batch-group, k-chunk), ascending.
// One warp per (bg, kc). 128 warps total. Also copies the 8 spike floats.
// Skipping zero-spike rows is bit-exact: fma(w, 0.0, acc) == acc.
// ---------------------------------------------------------------------------
__global__ void __launch_bounds__(256) compact_spikes() {
    int w    = (blockIdx.x * blockDim.x + threadIdx.x) >> 5;
    int lane = threadIdx.x & 31;
    if (w >= NBG * NKC) return;
    int bg = w >> 5;       // / NKC
    int kc = w & (NKC - 1);
    int base = kc * KCHUNK;
    int total = 0;
#pragma unroll
    for (int it = 0; it < 5; it++) {
        int r = it * 32 + lane;
        bool act = false;
        float4 a = make_float4(0.f, 0.f, 0.f, 0.f), b = a;
        if (r < KCHUNK) {
            const float4* p = (const float4*)&g_sfall[(base + r) * B_SZ + bg * 8];
            a = p[0]; b = p[1];
            // spikes are exactly 0.0f or 1.0f -> sum > 0 iff any nonzero
            act = (a.x + a.y + a.z + a.w + b.x + b.y + b.z + b.w) > 0.0f;
        }
        unsigned m = __ballot_sync(0xFFFFFFFFu, act);
        if (act) {
            int pos = total + __popc(m & ((1u << lane) - 1u));
            g_list[w * KCHUNK + pos] = (unsigned short)r;
            float4* q = (float4*)&g_spk[(w * KCHUNK + pos) * 8];
            q[0] = a; q[1] = b;
        }
        total += __popc(m);
    }
    if (lane == 0) g_cnt[w] = total;
}

// ---------------------------------------------------------------------------
// Kernel B (per step): sparse binary-spike GEMM partials.
// Grid: (16 col-tiles, 4 batch-groups, 8 by). Block: 8 warps = 4 ksub x 2 cw.
// Thread: 4 columns (lane*4, LDG.128 on W) x 8 batches (4 f32x2 acc per col).
// Iterates only the compacted active k list (ascending) for its chunk.
// In-block reduce over ksub ascending -> one partial per (c,b) per by.
// Bit-identical reduction tree to the previous passing kernel.
// ---------------------------------------------------------------------------
__global__ void __launch_bounds__(256, 3) step_gemm() {
    __shared__ unsigned long long sbuf[8][32][17];  // 16 u64 + pad

    const int w    = threadIdx.x >> 5;
    const int lane = threadIdx.x & 31;
    const int cw   = w & 1;          // column half within block
    const int ksub = w >> 1;         // 0..3
    const int bg   = blockIdx.y;     // batch group (8 batches)
    const int by   = blockIdx.z;     // partial index
    const int kc   = by * 4 + ksub;  // k-chunk 0..31
    const int c0   = blockIdx.x * 256 + cw * 128 + lane * 4;

    const int lw = bg * NKC + kc;
    const int n  = g_cnt[lw];
    const unsigned short* __restrict__ lst = &g_list[lw * KCHUNK];
    const float* __restrict__ spk = &g_spk[(size_t)lw * KCHUNK * 8];
    const int k0 = kc * KCHUNK;

    unsigned long long acc[4][4];
#pragma unroll
    for (int c = 0; c < 4; c++)
#pragma unroll
        for (int j = 0; j < 4; j++) acc[c][j] = 0ull;

#pragma unroll 4
    for (int i = 0; i < n; i++) {
        int kk = k0 + (int)lst[i];
        float4 wv = *(const float4*)&g_W[kk * NC + c0];
        const float4* sp4 = (const float4*)&spk[i * 8];
        float4 sA = sp4[0], sB = sp4[1];
        unsigned long long s2[4];
        s2[0] = pack2(__float_as_uint(sA.x), __float_as_uint(sA.y));
        s2[1] = pack2(__float_as_uint(sA.z), __float_as_uint(sA.w));
        s2[2] = pack2(__float_as_uint(sB.x), __float_as_uint(sB.y));
        s2[3] = pack2(__float_as_uint(sB.z), __float_as_uint(sB.w));
        unsigned wb[4] = {__float_as_uint(wv.x), __float_as_uint(wv.y),
                          __float_as_uint(wv.z), __float_as_uint(wv.w)};
#pragma unroll
        for (int c = 0; c < 4; c++) {
            unsigned long long w2 = pack2(wb[c], wb[c]);
#pragma unroll
            for (int j = 0; j < 4; j++)
                acc[c][j] = ffma2(w2, s2[j], acc[c][j]);
        }
    }

#pragma unroll
    for (int c = 0; c < 4; c++)
#pragma unroll
        for (int j = 0; j < 4; j++) sbuf[w][lane][c * 4 + j] = acc[c][j];
    __syncthreads();

    if (ksub == 0) {
#pragma unroll
        for (int ks = 1; ks < 4; ks++) {
#pragma unroll
            for (int c = 0; c < 4; c++)
#pragma unroll
                for (int j = 0; j < 4; j++)
                    acc[c][j] = fadd2(acc[c][j], sbuf[ks * 2 + cw][lane][c * 4 + j]);
        }
#pragma unroll
        for (int c = 0; c < 4; c++) {
            int cc = c0 + c;
#pragma unroll
            for (int j = 0; j < 4; j++) {
                unsigned long long v = acc[c][j];
                float flo = __uint_as_float((unsigned)v);
                float fhi = __uint_as_float((unsigned)(v >> 32));
                int b = bg * 8 + 2 * j;
                g_P[(cc * B_SZ + b) * NBY + by]     = flo;
                g_P[(cc * B_SZ + b + 1) * NBY + by] = fhi;
            }
        }
    }
}

// ---------------------------------------------------------------------------
// Kernel C (per step): ordered reduce of 8 partials, LIF update, threshold,
// write spikes to output, refresh spike-float table for step t+1.
// ---------------------------------------------------------------------------
__global__ void __launch_bounds__(256) step_update(float* __restrict__ out, int t) {
    int idx = blockIdx.x * blockDim.x + threadIdx.x;   // 0 .. 131071
    if (idx >= NC * B_SZ) return;
    int c = idx >> 5;
    int b = idx & 31;

    const float4* p = (const float4*)&g_P[(size_t)idx * NBY];
    float4 u = p[0], v = p[1];
    float I = u.x;
    I = __fadd_rn(I, u.y);
    I = __fadd_rn(I, u.z);
    I = __fadd_rn(I, u.w);
    I = __fadd_rn(I, v.x);
    I = __fadd_rn(I, v.y);
    I = __fadd_rn(I, v.z);
    I = __fadd_rn(I, v.w);

    float xd   = g_sfall[(NIN + c) * B_SZ + b];   // previous spike of this neuron
    float Vold = g_V[idx];
    float Vnew = __fadd_rn(__fmul_rn(__fmul_rn(ALPHA_F, Vold), __fsub_rn(1.0f, xd)), I);
    float s = (Vnew >= 1.0f) ? 1.0f : 0.0f;

    g_V[idx] = Vnew;
    g_sfall[(NIN + c) * B_SZ + b] = s;            // recurrent rows for step t+1

    int a = c >> 11;
    int n = c & (N_NEU - 1);
    out[XIS_SZ + a * SS_SZ + t * (B_SZ * N_NEU) + b * N_NEU + n] = s;

    if (c < NIN && t + 1 < T_STEPS)
        g_sfall[c * B_SZ + b] = g_sfin[((t + 1) * NIN + c) * B_SZ + b];
}

// ---------------------------------------------------------------------------
// Launch: prep (3 kernels) + 100 x (compact, gemm, update). Graph-capturable.
// ---------------------------------------------------------------------------
extern "C" void kernel_launch(void* const* d_in, const int* in_sizes, int n_in,
                              void* d_out, int out_size) {
    const float* rates = (const float*)d_in[0];
    const float* noise = (const float*)d_in[1];
    const float* Win   = (const float*)d_in[2];
    const float* Wrec  = (const float*)d_in[3];
    float* out = (float*)d_out;

    prep_spikes<<<(XIS_SZ + 255) / 256, 256>>>(rates, noise, out);
    pack_w<<<1024, 256>>>(Win, Wrec);
    init_state<<<(KROWS * B_SZ + 255) / 256, 256>>>();

    for (int t = 0; t < T_STEPS; t++) {
        compact_spikes<<<16, 256>>>();
        step_gemm<<<dim3(16, NBG, NBY), 256>>>();
        step_update<<<(NC * B_SZ) / 256, 256>>>(out, t);
    }
}

// round 4
// speedup vs baseline: 2.9705x; 1.4890x over previous
#include <cuda_runtime.h>
#include <cstdint>

// ---------------------------------------------------------------------------
// Problem constants
// ---------------------------------------------------------------------------
#define T_STEPS 100
#define B_SZ    32
#define NIN     512
#define N_NEU   2048
#define A_AR    2
#define NC      4096                    // A*N output columns, c = a*2048+n
#define KROWS   4608                    // NIN + NC input rows
#define KCHUNK  144                     // 4608 / 32 k-chunks
#define NKC     32                      // number of k-chunks
#define NBY     8                       // k-splits (4 chunks each)
#define NBG     4                       // batch groups of 8
#define XIS_SZ  (T_STEPS * B_SZ * NIN)  // 1,638,400
#define SS_SZ   (T_STEPS * B_SZ * N_NEU)// 6,553,600 per area
// alpha = float32(exp(-0.1))
#define ALPHA_F 0.9048374180359595731642491f

// ---------------------------------------------------------------------------
// Device-global scratch (static — no allocation anywhere)
// b-major layouts for coalesced update-kernel access.
// ---------------------------------------------------------------------------
__device__ float g_W[KROWS * NC];        // fused weights [k][c], 75.5 MB
__device__ float g_sfb[B_SZ * KROWS];    // spike floats [b][k] for current step
__device__ float g_V[B_SZ * NC];         // membrane V [b][c]
__device__ float g_P[B_SZ * NC * NBY];   // partials [b*NC+c][by]

// ---------------------------------------------------------------------------
// Packed f32x2 helpers (sm_103a) — immune to fast-math contraction
// ---------------------------------------------------------------------------
__device__ __forceinline__ unsigned long long pack2(unsigned lo, unsigned hi) {
    unsigned long long d;
    asm("mov.b64 %0, {%1, %2};" : "=l"(d) : "r"(lo), "r"(hi));
    return d;
}
__device__ __forceinline__ unsigned long long ffma2(unsigned long long a,
                                                    unsigned long long b,
                                                    unsigned long long c) {
    unsigned long long d;
    asm("fma.rn.f32x2 %0, %1, %2, %3;" : "=l"(d) : "l"(a), "l"(b), "l"(c));
    return d;
}
__device__ __forceinline__ unsigned long long fadd2(unsigned long long a,
                                                    unsigned long long b) {
    unsigned long long d;
    asm("add.rn.f32x2 %0, %1, %2;" : "=l"(d) : "l"(a), "l"(b));
    return d;
}

// ---------------------------------------------------------------------------
// Kernel 1: Poisson input spikes for all T, straight into the Xis output
// region (layout [t][b][i] — identical to the inputs). Pure elementwise.
// ---------------------------------------------------------------------------
__global__ void __launch_bounds__(256) prep_spikes(const float* __restrict__ rates,
                                                   const float* __restrict__ noise,
                                                   float* __restrict__ out) {
    int idx = blockIdx.x * blockDim.x + threadIdx.x;
    if (idx >= XIS_SZ) return;
    float rt = rates[idx];
    float nz = noise[idx];
    out[idx] = (nz < __fmul_rn(rt, 1e-3f)) ? 1.0f : 0.0f;
}

// ---------------------------------------------------------------------------
// Kernel 2: fuse Win [A,NIN,N] and Wrec [S,A,N,N] into g_W[k][c].
// ---------------------------------------------------------------------------
__global__ void pack_w(const float* __restrict__ Win,
                       const float* __restrict__ Wrec) {
    const int total4 = KROWS * NC / 4;
    for (int idx = blockIdx.x * blockDim.x + threadIdx.x; idx < total4;
         idx += gridDim.x * blockDim.x) {
        int e = idx << 2;
        int k = e >> 12;              // / 4096
        int c = e & (NC - 1);
        int a = c >> 11;
        int n = c & (N_NEU - 1);
        float4 v;
        if (k < NIN) {
            v = *(const float4*)&Win[(a * NIN + k) * N_NEU + n];
        } else {
            int kr = k - NIN;
            int s  = kr >> 11;
            int m  = kr & (N_NEU - 1);
            v = *(const float4*)&Wrec[(((s * A_AR + a) * N_NEU) + m) * (size_t)N_NEU + n];
        }
        *(float4*)&g_W[e] = v;
    }
}

// ---------------------------------------------------------------------------
// Kernel 3: init: V = 0; g_sfb[b][k] = Xi(t=0) for ff rows, 0 for rec rows.
// Reads Xi from the out buffer prep_spikes just wrote.
// ---------------------------------------------------------------------------
__global__ void __launch_bounds__(256) init_state(const float* __restrict__ out) {
    int idx = blockIdx.x * blockDim.x + threadIdx.x;
    if (idx < B_SZ * KROWS) {
        int b = idx / KROWS;
        int k = idx - b * KROWS;
        g_sfb[idx] = (k < NIN) ? out[b * NIN + k] : 0.0f;   // t=0 slice
    }
    if (idx < B_SZ * NC) g_V[idx] = 0.0f;
}

// ---------------------------------------------------------------------------
// Kernel B (per step): fused compact + sparse binary-spike GEMM partials.
// Grid: (16 col-tiles, 4 batch-groups, 8 by). Block: 8 warps = 4 ksub x 2 cw.
//
// Phase 1: warps 0..3 each build the ascending active-k list for chunk
//   kc = by*4 + warp (144 rows, active = any of 8 batch spikes nonzero,
//   checked by integer OR of exact {0.0,1.0} patterns) into shared, plus the
//   8 compacted spike floats per active row.
// Phase 2: all 8 warps run the FMA loop over their ksub's list (ascending k);
//   thread covers 4 columns (LDG.128 on W) x 8 batches (4 f32x2 accs/col).
// Reduce: ksub partials folded ascending in-block (bit-identical tree to the
//   previously passing kernel), one partial per (c,b) per by to g_P.
// ---------------------------------------------------------------------------
struct SmemP1 {
    unsigned list[4][KCHUNK];       // W byte offsets (k * NC * 4), ascending
    float    spk[4][KCHUNK][8];     // compacted spike floats
    int      cnt[4];
};
union SmemU {
    SmemP1 p1;
    unsigned long long sbuf[8][32][17];   // reduce buffer (16 u64 + pad)
};

__global__ void __launch_bounds__(256, 2) step_gemm() {
    __shared__ SmemU sm;

    const int w    = threadIdx.x >> 5;
    const int lane = threadIdx.x & 31;
    const int cw   = w & 1;          // column half within block
    const int ksub = w >> 1;         // 0..3
    const int bg   = blockIdx.y;     // batch group (8 batches)
    const int by   = blockIdx.z;     // partial index
    const int c0   = blockIdx.x * 256 + cw * 128 + lane * 4;

    // ---- Phase 1: warps 0..3 compact chunk (by*4 + w) for this bg ----
    if (w < 4) {
        const int kc = by * 4 + w;
        const int k0 = kc * KCHUNK;
        float    v[5][8];
        unsigned orv[5];
#pragma unroll
        for (int it = 0; it < 5; it++) {
            int r = it * 32 + lane;
            orv[it] = 0u;
#pragma unroll
            for (int b = 0; b < 8; b++) {
                float f = (r < KCHUNK) ? g_sfb[(bg * 8 + b) * KROWS + k0 + r] : 0.0f;
                v[it][b] = f;
                orv[it] |= __float_as_uint(f);
            }
        }
        int total = 0;
#pragma unroll
        for (int it = 0; it < 5; it++) {
            bool act = orv[it] != 0u;
            unsigned m = __ballot_sync(0xFFFFFFFFu, act);
            if (act) {
                int pos = total + __popc(m & ((1u << lane) - 1u));
                sm.p1.list[w][pos] = (unsigned)(k0 + it * 32 + lane) * (NC * 4);
#pragma unroll
                for (int b = 0; b < 8; b++) sm.p1.spk[w][pos][b] = v[it][b];
            }
            total += __popc(m);
        }
        if (lane == 0) sm.p1.cnt[w] = total;
    }
    __syncthreads();

    // ---- Phase 2: sparse FMA loop over this warp's chunk list ----
    const int n = sm.p1.cnt[ksub];
    const unsigned* __restrict__ lst = sm.p1.list[ksub];
    const float*    __restrict__ spk = &sm.p1.spk[ksub][0][0];
    const char* __restrict__ wbase = (const char*)g_W + (size_t)c0 * 4;

    unsigned long long acc[4][4];
#pragma unroll
    for (int c = 0; c < 4; c++)
#pragma unroll
        for (int j = 0; j < 4; j++) acc[c][j] = 0ull;

#pragma unroll 4
    for (int i = 0; i < n; i++) {
        unsigned off = lst[i];
        float4 wv = *(const float4*)(wbase + off);
        float4 sA = *(const float4*)&spk[i * 8];
        float4 sB = *(const float4*)&spk[i * 8 + 4];
        unsigned long long s2[4];
        s2[0] = pack2(__float_as_uint(sA.x), __float_as_uint(sA.y));
        s2[1] = pack2(__float_as_uint(sA.z), __float_as_uint(sA.w));
        s2[2] = pack2(__float_as_uint(sB.x), __float_as_uint(sB.y));
        s2[3] = pack2(__float_as_uint(sB.z), __float_as_uint(sB.w));
        unsigned wb[4] = {__float_as_uint(wv.x), __float_as_uint(wv.y),
                          __float_as_uint(wv.z), __float_as_uint(wv.w)};
#pragma unroll
        for (int c = 0; c < 4; c++) {
            unsigned long long w2 = pack2(wb[c], wb[c]);
#pragma unroll
            for (int j = 0; j < 4; j++)
                acc[c][j] = ffma2(w2, s2[j], acc[c][j]);
        }
    }

    __syncthreads();   // all phase-1 data consumed; safe to reuse shared

#pragma unroll
    for (int c = 0; c < 4; c++)
#pragma unroll
        for (int j = 0; j < 4; j++) sm.sbuf[w][lane][c * 4 + j] = acc[c][j];
    __syncthreads();

    if (ksub == 0) {
#pragma unroll
        for (int ks = 1; ks < 4; ks++) {
#pragma unroll
            for (int c = 0; c < 4; c++)
#pragma unroll
                for (int j = 0; j < 4; j++)
                    acc[c][j] = fadd2(acc[c][j], sm.sbuf[ks * 2 + cw][lane][c * 4 + j]);
        }
#pragma unroll
        for (int c = 0; c < 4; c++) {
            int cc = c0 + c;
#pragma unroll
            for (int j = 0; j < 4; j++) {
                unsigned long long v = acc[c][j];
                float flo = __uint_as_float((unsigned)v);
                float fhi = __uint_as_float((unsigned)(v >> 32));
                int b = bg * 8 + 2 * j;
                g_P[((size_t)(b)     * NC + cc) * NBY + by] = flo;
                g_P[((size_t)(b + 1) * NC + cc) * NBY + by] = fhi;
            }
        }
    }
}

// ---------------------------------------------------------------------------
// Kernel C (per step): ordered reduce of 8 partials, LIF update, threshold,
// write spikes, refresh spike table for t+1. Thread = b*4096 + c -> every
// global access coalesced.
// ---------------------------------------------------------------------------
__global__ void __launch_bounds__(256) step_update(float* __restrict__ out, int t) {
    int idx = blockIdx.x * blockDim.x + threadIdx.x;   // 0 .. 131071
    if (idx >= B_SZ * NC) return;
    int b = idx >> 12;
    int c = idx & (NC - 1);

    const float4* p = (const float4*)&g_P[(size_t)idx * NBY];
    float4 u = p[0], v = p[1];
    float I = u.x;
    I = __fadd_rn(I, u.y);
    I = __fadd_rn(I, u.z);
    I = __fadd_rn(I, u.w);
    I = __fadd_rn(I, v.x);
    I = __fadd_rn(I, v.y);
    I = __fadd_rn(I, v.z);
    I = __fadd_rn(I, v.w);

    int sfi = b * KROWS + NIN + c;
    float xd   = g_sfb[sfi];            // previous spike of this neuron
    float Vold = g_V[idx];
    float Vnew = __fadd_rn(__fmul_rn(__fmul_rn(ALPHA_F, Vold), __fsub_rn(1.0f, xd)), I);
    float s = (Vnew >= 1.0f) ? 1.0f : 0.0f;

    g_V[idx] = Vnew;
    g_sfb[sfi] = s;                     // recurrent rows for step t+1

    int a = c >> 11;
    int n = c & (N_NEU - 1);
    out[XIS_SZ + a * SS_SZ + t * (B_SZ * N_NEU) + b * N_NEU + n] = s;

    // feedforward rows for step t+1 (read from the Xis region of out)
    if (c < NIN && t + 1 < T_STEPS)
        g_sfb[b * KROWS + c] = out[(t + 1) * (B_SZ * NIN) + b * NIN + c];
}

// ---------------------------------------------------------------------------
// Launch: prep (3 kernels) + 100 x (gemm, update). Graph-capturable.
// ---------------------------------------------------------------------------
extern "C" void kernel_launch(void* const* d_in, const int* in_sizes, int n_in,
                              void* d_out, int out_size) {
    const float* rates = (const float*)d_in[0];
    const float* noise = (const float*)d_in[1];
    const float* Win   = (const float*)d_in[2];
    const float* Wrec  = (const float*)d_in[3];
    float* out = (float*)d_out;

    prep_spikes<<<(XIS_SZ + 255) / 256, 256>>>(rates, noise, out);
    pack_w<<<1024, 256>>>(Win, Wrec);
    init_state<<<(B_SZ * KROWS + 255) / 256, 256>>>(out);

    for (int t = 0; t < T_STEPS; t++) {
        step_gemm<<<dim3(16, NBG, NBY), 256>>>();
        step_update<<<(B_SZ * NC) / 256, 256>>>(out, t);
    }
}